// round 1
// baseline (speedup 1.0000x reference)
#include <cuda_runtime.h>

#define TPB 256
#define NXC 64
#define NQC 64
#define NUC 16

// SMEM: A(4096) B1(4096) B2(1024) C1(4096) D11(4096) D12(1024) bv(64) bx(64)
#define SMEM_FLOATS (NXC*NXC + NXC*NQC + NXC*NUC + NQC*NXC + NQC*NQC + NQC*NUC + NQC + NXC)
#define SMEM_BYTES (SMEM_FLOATS * 4)

__device__ __forceinline__ void cpy4(float* dst, const float* src, int n) {
    for (int i = threadIdx.x; i < (n >> 2); i += TPB)
        reinterpret_cast<float4*>(dst)[i] = reinterpret_cast<const float4*>(src)[i];
}

__global__ __launch_bounds__(TPB, 1)
void ren_fused_kernel(const float* __restrict__ x, const float* __restrict__ u,
                      const float* __restrict__ A, const float* __restrict__ B1,
                      const float* __restrict__ B2, const float* __restrict__ C1,
                      const float* __restrict__ D11, const float* __restrict__ D12,
                      const float* __restrict__ bv, const float* __restrict__ bx,
                      float* __restrict__ out, int n) {
    extern __shared__ float sm[];
    float* sA   = sm;
    float* sB1  = sA   + NXC*NXC;
    float* sB2  = sB1  + NXC*NQC;
    float* sC1  = sB2  + NXC*NUC;
    float* sD11 = sC1  + NQC*NXC;
    float* sD12 = sD11 + NQC*NQC;
    float* sbv  = sD12 + NQC*NUC;
    float* sbx  = sbv  + NQC;

    cpy4(sA, A, NXC*NXC);
    cpy4(sB1, B1, NXC*NQC);
    cpy4(sB2, B2, NXC*NUC);
    cpy4(sC1, C1, NQC*NXC);
    cpy4(sD11, D11, NQC*NQC);
    cpy4(sD12, D12, NQC*NUC);
    cpy4(sbv, bv, NQC);
    cpy4(sbx, bx, NXC);

    const int row = blockIdx.x * TPB + threadIdx.x;

    float xr[NXC];
    float ur[NUC];
    if (row < n) {
        const float4* xp = reinterpret_cast<const float4*>(x + (size_t)row * NXC);
        #pragma unroll
        for (int j = 0; j < NXC/4; ++j) reinterpret_cast<float4*>(xr)[j] = xp[j];
        const float4* up = reinterpret_cast<const float4*>(u + (size_t)row * NUC);
        #pragma unroll
        for (int j = 0; j < NUC/4; ++j) reinterpret_cast<float4*>(ur)[j] = up[j];
    }
    __syncthreads();
    if (row >= n) return;

    // ---- Forward substitution: w[i] = relu(bv[i] + C1[i].x + D12[i].u + D11[i,0:i].w)
    // Fully unrolled so w[] stays in registers (all indices compile-time).
    float w[NQC];
    #pragma unroll
    for (int i = 0; i < NQC; ++i) {
        const float* c1r  = sC1  + i * NXC;
        const float* d12r = sD12 + i * NUC;
        const float* d11r = sD11 + i * NQC;
        float a0 = sbv[i], a1 = 0.f, a2 = 0.f, a3 = 0.f;
        #pragma unroll
        for (int j = 0; j < NXC; j += 4) {
            float4 c = *reinterpret_cast<const float4*>(c1r + j);
            a0 = fmaf(c.x, xr[j+0], a0);
            a1 = fmaf(c.y, xr[j+1], a1);
            a2 = fmaf(c.z, xr[j+2], a2);
            a3 = fmaf(c.w, xr[j+3], a3);
        }
        #pragma unroll
        for (int j = 0; j < NUC; j += 4) {
            float4 c = *reinterpret_cast<const float4*>(d12r + j);
            a0 = fmaf(c.x, ur[j+0], a0);
            a1 = fmaf(c.y, ur[j+1], a1);
            a2 = fmaf(c.z, ur[j+2], a2);
            a3 = fmaf(c.w, ur[j+3], a3);
        }
        #pragma unroll
        for (int j = 0; j + 3 < i; j += 4) {
            float4 c = *reinterpret_cast<const float4*>(d11r + j);
            a0 = fmaf(c.x, w[j+0], a0);
            a1 = fmaf(c.y, w[j+1], a1);
            a2 = fmaf(c.z, w[j+2], a2);
            a3 = fmaf(c.w, w[j+3], a3);
        }
        #pragma unroll
        for (int j = (i & ~3); j < i; ++j)
            a0 = fmaf(d11r[j], w[j], a0);
        float v = (a0 + a1) + (a2 + a3);
        w[i] = v > 0.f ? v : 0.f;
    }

    // ---- Output: out[k] = bx[k] + A[k].x + B1[k].w + B2[k].u
    float* op = out + (size_t)row * NXC;
    #pragma unroll 2
    for (int k = 0; k < NXC; ++k) {
        const float* ar  = sA  + k * NXC;
        const float* b1r = sB1 + k * NQC;
        const float* b2r = sB2 + k * NUC;
        float a0 = sbx[k], a1 = 0.f, a2 = 0.f, a3 = 0.f;
        #pragma unroll
        for (int j = 0; j < NXC; j += 4) {
            float4 c = *reinterpret_cast<const float4*>(ar + j);
            a0 = fmaf(c.x, xr[j+0], a0);
            a1 = fmaf(c.y, xr[j+1], a1);
            a2 = fmaf(c.z, xr[j+2], a2);
            a3 = fmaf(c.w, xr[j+3], a3);
            float4 b = *reinterpret_cast<const float4*>(b1r + j);
            a0 = fmaf(b.x, w[j+0], a0);
            a1 = fmaf(b.y, w[j+1], a1);
            a2 = fmaf(b.z, w[j+2], a2);
            a3 = fmaf(b.w, w[j+3], a3);
        }
        #pragma unroll
        for (int j = 0; j < NUC; j += 4) {
            float4 c = *reinterpret_cast<const float4*>(b2r + j);
            a0 = fmaf(c.x, ur[j+0], a0);
            a1 = fmaf(c.y, ur[j+1], a1);
            a2 = fmaf(c.z, ur[j+2], a2);
            a3 = fmaf(c.w, ur[j+3], a3);
        }
        op[k] = (a0 + a1) + (a2 + a3);
    }
}

extern "C" void kernel_launch(void* const* d_in, const int* in_sizes, int n_in,
                              void* d_out, int out_size) {
    const float* x   = (const float*)d_in[0];
    const float* u   = (const float*)d_in[1];
    const float* A   = (const float*)d_in[2];
    const float* B1  = (const float*)d_in[3];
    const float* B2  = (const float*)d_in[4];
    const float* C1  = (const float*)d_in[5];
    const float* D11 = (const float*)d_in[6];
    const float* D12 = (const float*)d_in[7];
    const float* bv  = (const float*)d_in[8];
    const float* bx  = (const float*)d_in[9];
    float* out = (float*)d_out;

    const int n = in_sizes[0] / NXC;   // 262144 rows
    cudaFuncSetAttribute(ren_fused_kernel,
                         cudaFuncAttributeMaxDynamicSharedMemorySize, SMEM_BYTES);
    const int blocks = (n + TPB - 1) / TPB;
    ren_fused_kernel<<<blocks, TPB, SMEM_BYTES>>>(x, u, A, B1, B2, C1, D11, D12,
                                                  bv, bx, out, n);
}

// round 2
// speedup vs baseline: 1.4080x; 1.4080x over previous
#include <cuda_runtime.h>

typedef unsigned long long u64;

#define TPB 256
#define NXC 64
#define NQC 64
#define NUC 16

// SMEM: A(4096) B1(4096) B2(1024) C1(4096) D11(4096) D12(1024) bv(64) bx(64)
#define SMEM_FLOATS (NXC*NXC + NXC*NQC + NXC*NUC + NQC*NXC + NQC*NQC + NQC*NUC + NQC + NXC)
#define SMEM_BYTES (SMEM_FLOATS * 4)

// Packed f32x2 FMA (Blackwell): one instruction = two fp32 FMAs, identical rounding.
#define FMA2(d, a, b, c) \
    asm("fma.rn.f32x2 %0, %1, %2, %3;" : "=l"(d) : "l"(a), "l"(b), "l"(c))

__device__ __forceinline__ u64 pack2(float lo, float hi) {
    u64 r; asm("mov.b64 %0, {%1, %2};" : "=l"(r) : "f"(lo), "f"(hi)); return r;
}
__device__ __forceinline__ float2 unpack2(u64 v) {
    float2 r; asm("mov.b64 {%0, %1}, %2;" : "=f"(r.x), "=f"(r.y) : "l"(v)); return r;
}

__device__ __forceinline__ void cpy4(float* dst, const float* src, int n) {
    for (int i = threadIdx.x; i < (n >> 2); i += TPB)
        reinterpret_cast<float4*>(dst)[i] = reinterpret_cast<const float4*>(src)[i];
}

__global__ __launch_bounds__(TPB, 1)
void ren_fused_kernel(const float* __restrict__ x, const float* __restrict__ u,
                      const float* __restrict__ A, const float* __restrict__ B1,
                      const float* __restrict__ B2, const float* __restrict__ C1,
                      const float* __restrict__ D11, const float* __restrict__ D12,
                      const float* __restrict__ bv, const float* __restrict__ bx,
                      float* __restrict__ out, int n) {
    extern __shared__ float sm[];
    float* sA   = sm;
    float* sB1  = sA   + NXC*NXC;
    float* sB2  = sB1  + NXC*NQC;
    float* sC1  = sB2  + NXC*NUC;
    float* sD11 = sC1  + NQC*NXC;
    float* sD12 = sD11 + NQC*NQC;
    float* sbv  = sD12 + NQC*NUC;
    float* sbx  = sbv  + NQC;

    cpy4(sA, A, NXC*NXC);
    cpy4(sB1, B1, NXC*NQC);
    cpy4(sB2, B2, NXC*NUC);
    cpy4(sC1, C1, NQC*NXC);
    cpy4(sD11, D11, NQC*NQC);
    cpy4(sD12, D12, NQC*NUC);
    cpy4(sbv, bv, NQC);
    cpy4(sbx, bx, NXC);

    const int row = blockIdx.x * TPB + threadIdx.x;

    u64 xr2[NXC/2];   // x row, packed pairs (x[2j], x[2j+1])
    u64 ur2[NUC/2];   // u row, packed pairs
    if (row < n) {
        const ulonglong2* xp = reinterpret_cast<const ulonglong2*>(x + (size_t)row * NXC);
        #pragma unroll
        for (int j = 0; j < NXC/4; ++j) { ulonglong2 q = xp[j]; xr2[2*j] = q.x; xr2[2*j+1] = q.y; }
        const ulonglong2* up = reinterpret_cast<const ulonglong2*>(u + (size_t)row * NUC);
        #pragma unroll
        for (int j = 0; j < NUC/4; ++j) { ulonglong2 q = up[j]; ur2[2*j] = q.x; ur2[2*j+1] = q.y; }
    }
    __syncthreads();
    if (row >= n) return;

    // ---- Forward substitution: w[i] = relu(bv[i] + C1[i].x + D12[i].u + D11[i,0:i].w)
    // w kept as packed pairs wv[p] = (w[2p], w[2p+1]); fully unrolled so all indices static.
    u64 wv[NQC/2];
    float wprev = 0.f;   // holds w[i-1] between even->odd steps
    #pragma unroll
    for (int i = 0; i < NQC; ++i) {
        const float* c1r  = sC1  + i * NXC;
        const float* d12r = sD12 + i * NUC;
        const float* d11r = sD11 + i * NQC;
        u64 a0 = pack2(sbv[i], 0.f), a1 = 0ull, a2 = 0ull, a3 = 0ull;
        #pragma unroll
        for (int j = 0; j < NXC; j += 8) {
            ulonglong2 q0 = *reinterpret_cast<const ulonglong2*>(c1r + j);
            ulonglong2 q1 = *reinterpret_cast<const ulonglong2*>(c1r + j + 4);
            FMA2(a0, q0.x, xr2[j/2 + 0], a0);
            FMA2(a1, q0.y, xr2[j/2 + 1], a1);
            FMA2(a2, q1.x, xr2[j/2 + 2], a2);
            FMA2(a3, q1.y, xr2[j/2 + 3], a3);
        }
        #pragma unroll
        for (int j = 0; j < NUC; j += 8) {
            ulonglong2 q0 = *reinterpret_cast<const ulonglong2*>(d12r + j);
            ulonglong2 q1 = *reinterpret_cast<const ulonglong2*>(d12r + j + 4);
            FMA2(a0, q0.x, ur2[j/2 + 0], a0);
            FMA2(a1, q0.y, ur2[j/2 + 1], a1);
            FMA2(a2, q1.x, ur2[j/2 + 2], a2);
            FMA2(a3, q1.y, ur2[j/2 + 3], a3);
        }
        // triangular part: full pairs 0..(i>>1)-1
        #pragma unroll
        for (int jp = 0; jp < (i >> 1); ++jp) {
            u64 q = *reinterpret_cast<const u64*>(d11r + 2*jp);
            if ((jp & 3) == 0)      FMA2(a0, q, wv[jp], a0);
            else if ((jp & 3) == 1) FMA2(a1, q, wv[jp], a1);
            else if ((jp & 3) == 2) FMA2(a2, q, wv[jp], a2);
            else                    FMA2(a3, q, wv[jp], a3);
        }
        float2 f0 = unpack2(a0), f1 = unpack2(a1), f2 = unpack2(a2), f3 = unpack2(a3);
        float v = ((f0.x + f0.y) + (f1.x + f1.y)) + ((f2.x + f2.y) + (f3.x + f3.y));
        if (i & 1)   // odd i: one leftover scalar term d11[i][i-1] * w[i-1]
            v = fmaf(d11r[i-1], wprev, v);
        float vr = v > 0.f ? v : 0.f;
        if (i & 1) wv[i >> 1] = pack2(wprev, vr);
        else       wprev = vr;
    }

    // ---- Output: out[k] = bx[k] + A[k].x + B1[k].w + B2[k].u, 4 outputs per STG.128
    float* op = out + (size_t)row * NXC;
    #pragma unroll 2
    for (int kk = 0; kk < NXC; kk += 4) {
        float res[4];
        #pragma unroll
        for (int q = 0; q < 4; ++q) {
            const int k = kk + q;
            const float* ar  = sA  + k * NXC;
            const float* b1r = sB1 + k * NQC;
            const float* b2r = sB2 + k * NUC;
            u64 a0 = pack2(sbx[k], 0.f), a1 = 0ull, a2 = 0ull, a3 = 0ull;
            #pragma unroll
            for (int j = 0; j < NXC; j += 8) {
                ulonglong2 qa0 = *reinterpret_cast<const ulonglong2*>(ar + j);
                ulonglong2 qa1 = *reinterpret_cast<const ulonglong2*>(ar + j + 4);
                FMA2(a0, qa0.x, xr2[j/2 + 0], a0);
                FMA2(a1, qa0.y, xr2[j/2 + 1], a1);
                FMA2(a2, qa1.x, xr2[j/2 + 2], a2);
                FMA2(a3, qa1.y, xr2[j/2 + 3], a3);
                ulonglong2 qb0 = *reinterpret_cast<const ulonglong2*>(b1r + j);
                ulonglong2 qb1 = *reinterpret_cast<const ulonglong2*>(b1r + j + 4);
                FMA2(a0, qb0.x, wv[j/2 + 0], a0);
                FMA2(a1, qb0.y, wv[j/2 + 1], a1);
                FMA2(a2, qb1.x, wv[j/2 + 2], a2);
                FMA2(a3, qb1.y, wv[j/2 + 3], a3);
            }
            #pragma unroll
            for (int j = 0; j < NUC; j += 8) {
                ulonglong2 q0 = *reinterpret_cast<const ulonglong2*>(b2r + j);
                ulonglong2 q1 = *reinterpret_cast<const ulonglong2*>(b2r + j + 4);
                FMA2(a0, q0.x, ur2[j/2 + 0], a0);
                FMA2(a1, q0.y, ur2[j/2 + 1], a1);
                FMA2(a2, q1.x, ur2[j/2 + 2], a2);
                FMA2(a3, q1.y, ur2[j/2 + 3], a3);
            }
            float2 f0 = unpack2(a0), f1 = unpack2(a1), f2 = unpack2(a2), f3 = unpack2(a3);
            res[q] = ((f0.x + f0.y) + (f1.x + f1.y)) + ((f2.x + f2.y) + (f3.x + f3.y));
        }
        *reinterpret_cast<float4*>(op + kk) = make_float4(res[0], res[1], res[2], res[3]);
    }
}

extern "C" void kernel_launch(void* const* d_in, const int* in_sizes, int n_in,
                              void* d_out, int out_size) {
    const float* x   = (const float*)d_in[0];
    const float* u   = (const float*)d_in[1];
    const float* A   = (const float*)d_in[2];
    const float* B1  = (const float*)d_in[3];
    const float* B2  = (const float*)d_in[4];
    const float* C1  = (const float*)d_in[5];
    const float* D11 = (const float*)d_in[6];
    const float* D12 = (const float*)d_in[7];
    const float* bv  = (const float*)d_in[8];
    const float* bx  = (const float*)d_in[9];
    float* out = (float*)d_out;

    const int n = in_sizes[0] / NXC;   // 262144 rows
    cudaFuncSetAttribute(ren_fused_kernel,
                         cudaFuncAttributeMaxDynamicSharedMemorySize, SMEM_BYTES);
    const int blocks = (n + TPB - 1) / TPB;
    ren_fused_kernel<<<blocks, TPB, SMEM_BYTES>>>(x, u, A, B1, B2, C1, D11, D12,
                                                  bv, bx, out, n);
}